// round 10
// baseline (speedup 1.0000x reference)
#include <cuda_runtime.h>
#include <cuda_bf16.h>
#include <cstdint>

#define N_NODES 100000
#define N_EDGES 600000
#define F_IN 128
#define HID 128
#define CLS 16

// ---------------- scratch (device globals: no allocation allowed) ----------
__device__ float g_deg[N_NODES];                          // in-degree (float)
__device__ int   g_degi[N_NODES];                         // in-degree (int)
__device__ int   g_off[N_NODES];                          // CSR offsets
__device__ int   g_cur[N_NODES];                          // placement cursors
__device__ int   g_eid[N_EDGES];                          // CSR src list
__device__ float4 g_agg4[(size_t)N_NODES * F_IN / 4];     // layer-1 neighbor MEAN
__device__ float4 g_h4[(size_t)N_NODES * HID / 4];        // layer-1 output
__device__ float4 g_t4[(size_t)N_NODES * CLS / 4];        // h @ W2_l (pre-aggregation)
__device__ float4 g_agg24[(size_t)N_NODES * CLS / 4];     // layer-2 neighbor sum of t
__device__ int g_src[N_EDGES];
__device__ int g_dst[N_EDGES];
__device__ int g_fmt64;                                    // 1 if edge_index is int64
// bf16 hi/lo images of W1l/W1r as B[n][k] (k contiguous = col-major for mma.sync)
__device__ __align__(16) uint16_t g_Bh_img[2][128 * 128];
__device__ __align__(16) uint16_t g_Bl_img[2][128 * 128];

#define g_h    ((float*)g_h4)
#define g_t    ((float*)g_t4)
#define g_agg2 ((float*)g_agg24)

// ---------------- mma.sync helper (portable sm_80+ HMMA path) ---------------
__device__ __forceinline__ void mma_bf16(float* d, const uint32_t* a,
                                         const uint32_t* b) {
    asm volatile(
        "mma.sync.aligned.m16n8k16.row.col.f32.bf16.bf16.f32 "
        "{%0,%1,%2,%3}, {%4,%5,%6,%7}, {%8,%9}, {%0,%1,%2,%3};"
        : "+f"(d[0]), "+f"(d[1]), "+f"(d[2]), "+f"(d[3])
        : "r"(a[0]), "r"(a[1]), "r"(a[2]), "r"(a[3]), "r"(b[0]), "r"(b[1]));
}

// smem layout for gemm1: 4 padded bf16 panels [128 rows][136 elems]
#define PADK 136
#define ROWB (PADK * 2)            // 272 bytes per row
#define ASZ  (128 * ROWB)          // 34816 bytes per panel
#define OFF_AH 0
#define OFF_AL (ASZ)
#define OFF_BH (2 * ASZ)
#define OFF_BL (3 * ASZ)
#define SMEM_G1 (4 * ASZ)          // 139264 bytes

// ---------------- kernel 0a: detect edge_index dtype ------------------------
__global__ void detect_kernel(const int* __restrict__ ew) {
    __shared__ int sacc[256];
    int acc = 0;
    for (int i = threadIdx.x; i < 4096; i += 256)
        acc |= ew[2 * i + 1];
    sacc[threadIdx.x] = acc;
    __syncthreads();
    if (threadIdx.x == 0) {
        int t = 0;
        for (int i = 0; i < 256; i++) t |= sacc[i];
        g_fmt64 = (t == 0) ? 1 : 0;
    }
}

// ---------------- kernel 0b: decode edges + count degrees -------------------
__global__ void __launch_bounds__(256)
decode_kernel(const int* __restrict__ ew) {
    int e = blockIdx.x * blockDim.x + threadIdx.x;
    if (e >= N_EDGES) return;
    int s, d;
    if (g_fmt64) {
        s = ew[2 * e];
        d = ew[2 * (N_EDGES + e)];
    } else {
        s = ew[e];
        d = ew[N_EDGES + e];
    }
    g_src[e] = s;
    g_dst[e] = d;
    atomicAdd(&g_degi[d], 1);
}

// ---------------- kernel 0c: exclusive scan of degrees (1 block) ------------
__global__ void __launch_bounds__(1024)
scan_kernel() {
    __shared__ int ssum[1024];
    int t = threadIdx.x;
    const int CH = (N_NODES + 1023) / 1024;   // 98
    int lo = t * CH, hi = min(lo + CH, N_NODES);
    int s = 0;
    for (int i = lo; i < hi; i++) s += g_degi[i];
    ssum[t] = s;
    __syncthreads();
    for (int o = 1; o < 1024; o <<= 1) {
        int u = (t >= o) ? ssum[t - o] : 0;
        __syncthreads();
        ssum[t] += u;
        __syncthreads();
    }
    int run = ssum[t] - s;   // exclusive base for this chunk
    for (int i = lo; i < hi; i++) {
        g_off[i] = run;
        g_cur[i] = run;
        run += g_degi[i];
    }
}

// ---------------- kernel 0d: CSR placement ----------------------------------
__global__ void __launch_bounds__(256)
place_kernel() {
    int e = blockIdx.x * blockDim.x + threadIdx.x;
    if (e >= N_EDGES) return;
    int pos = atomicAdd(&g_cur[g_dst[e]], 1);
    g_eid[pos] = g_src[e];
}

// ---------------- kernel 0e: convert W1l/W1r -> bf16 hi/lo B[n][k] ----------
__global__ void __launch_bounds__(256)
wconv_kernel(const float* __restrict__ W1l, const float* __restrict__ W1r) {
    int id = blockIdx.x * blockDim.x + threadIdx.x;
    if (id >= 2 * 128 * 128) return;
    int p = id >> 14, rem = id & 16383;
    int n = rem >> 7, k = rem & 127;
    const float* W = p ? W1r : W1l;
    float w = W[k * 128 + n];                 // W[k][n] -> B[n][k]
    __nv_bfloat16 h = __float2bfloat16(w);
    __nv_bfloat16 l = __float2bfloat16(w - __bfloat162float(h));
    g_Bh_img[p][n * 128 + k] = *(uint16_t*)&h;
    g_Bl_img[p][n * 128 + k] = *(uint16_t*)&l;
}

// ---------------- kernel 1: gather-mean x over CSR -> g_agg (mean), g_deg ---
// one warp per dst node; lane = one float4 of the 128-float feature row
__global__ void __launch_bounds__(256)
gather1_kernel(const float* __restrict__ x) {
    int gw = (blockIdx.x * blockDim.x + threadIdx.x) >> 5;
    int lane = threadIdx.x & 31;
    if (gw >= N_NODES) return;
    int beg = g_off[gw];
    int deg = g_degi[gw];
    float4 acc = make_float4(0.f, 0.f, 0.f, 0.f);
    int c = 0;
    while (c < deg) {
        int cnt = min(deg - c, 32);
        int idx = (lane < cnt) ? g_eid[beg + c + lane] : 0;
#pragma unroll 4
        for (int j = 0; j < cnt; j++) {
            int s = __shfl_sync(0xffffffffu, idx, j);
            float4 v = ((const float4*)x)[(size_t)s * 32 + lane];
            acc.x += v.x; acc.y += v.y; acc.z += v.z; acc.w += v.w;
        }
        c += cnt;
    }
    float invd = 1.0f / fmaxf((float)deg, 1.0f);
    acc.x *= invd; acc.y *= invd; acc.z *= invd; acc.w *= invd;
    g_agg4[(size_t)gw * 32 + lane] = acc;
    if (lane == 0) g_deg[gw] = (float)deg;
}

// ---------------- kernel 2: h = relu(mean@W1l + b1 + x@W1r) -----------------
// mma.sync bf16 3-term split GEMM. CTA = 128x128 tile, 8 warps (4m x 2n),
// warp tile 32x64. K=256 in two phases, accumulated in register fragments.
__global__ void __launch_bounds__(256, 1)
gemm1_kernel(const float* __restrict__ x, const float* __restrict__ b1) {
    extern __shared__ __align__(16) char sm[];
    __shared__ float s_bias[128];

    int tid = threadIdx.x, wid = tid >> 5, lane = tid & 31;
    int qr = lane >> 2, qc = lane & 3;
    int row0 = blockIdx.x * 128;
    int r0 = (wid & 3) * 32;       // warp m-offset
    int c0 = (wid >> 2) * 64;      // warp n-offset

    if (tid < 128) s_bias[tid] = b1[tid];

    float d[2][8][4];
#pragma unroll
    for (int mi = 0; mi < 2; mi++)
#pragma unroll
        for (int nj = 0; nj < 8; nj++)
#pragma unroll
            for (int v = 0; v < 4; v++) d[mi][nj][v] = 0.f;

#pragma unroll 1
    for (int phase = 0; phase < 2; phase++) {
        __syncthreads();   // protect smem reuse across phases (and bias init)

        // ---- A conversion: fp32 -> bf16 hi/lo into padded panels ----
        for (int f = tid; f < 128 * 32; f += 256) {
            int r = f >> 5, q = f & 31;          // q = float4 index over k
            int gi = row0 + r;
            float4 v = make_float4(0.f, 0.f, 0.f, 0.f);
            if (gi < N_NODES) {
                v = phase ? ((const float4*)(x + (size_t)gi * 128))[q]
                          : g_agg4[(size_t)gi * 32 + q];
            }
            __nv_bfloat16 h0 = __float2bfloat16(v.x), h1 = __float2bfloat16(v.y);
            __nv_bfloat16 h2 = __float2bfloat16(v.z), h3 = __float2bfloat16(v.w);
            __nv_bfloat16 l0 = __float2bfloat16(v.x - __bfloat162float(h0));
            __nv_bfloat16 l1 = __float2bfloat16(v.y - __bfloat162float(h1));
            __nv_bfloat16 l2 = __float2bfloat16(v.z - __bfloat162float(h2));
            __nv_bfloat16 l3 = __float2bfloat16(v.w - __bfloat162float(h3));
            uint64_t hp = (uint64_t)(*(uint16_t*)&h0)
                        | ((uint64_t)(*(uint16_t*)&h1) << 16)
                        | ((uint64_t)(*(uint16_t*)&h2) << 32)
                        | ((uint64_t)(*(uint16_t*)&h3) << 48);
            uint64_t lp = (uint64_t)(*(uint16_t*)&l0)
                        | ((uint64_t)(*(uint16_t*)&l1) << 16)
                        | ((uint64_t)(*(uint16_t*)&l2) << 32)
                        | ((uint64_t)(*(uint16_t*)&l3) << 48);
            int off = r * ROWB + q * 8;          // q*4 bf16 = 8 bytes
            *(uint64_t*)(sm + OFF_AH + off) = hp;
            *(uint64_t*)(sm + OFF_AL + off) = lp;
        }
        // ---- B copy: unpadded [n][128] images -> padded panels ----
        for (int i = tid; i < 2048; i += 256) {  // 128 rows x 16 float4
            int r = i >> 4, w = i & 15;
            int dst = r * ROWB + w * 16;
            *(float4*)(sm + OFF_BH + dst) = ((const float4*)g_Bh_img[phase])[i];
            *(float4*)(sm + OFF_BL + dst) = ((const float4*)g_Bl_img[phase])[i];
        }
        __syncthreads();

        // ---- mainloop: 8 k16-steps ----
#pragma unroll 1
        for (int ks = 0; ks < 8; ks++) {
            int kb = ks * 16;
            uint32_t ah[2][4], al[2][4];
#pragma unroll
            for (int mi = 0; mi < 2; mi++) {
                int ro = (r0 + mi * 16 + qr) * ROWB + (kb + 2 * qc) * 2;
                ah[mi][0] = *(const uint32_t*)(sm + OFF_AH + ro);
                ah[mi][1] = *(const uint32_t*)(sm + OFF_AH + ro + 8 * ROWB);
                ah[mi][2] = *(const uint32_t*)(sm + OFF_AH + ro + 16);
                ah[mi][3] = *(const uint32_t*)(sm + OFF_AH + ro + 8 * ROWB + 16);
                al[mi][0] = *(const uint32_t*)(sm + OFF_AL + ro);
                al[mi][1] = *(const uint32_t*)(sm + OFF_AL + ro + 8 * ROWB);
                al[mi][2] = *(const uint32_t*)(sm + OFF_AL + ro + 16);
                al[mi][3] = *(const uint32_t*)(sm + OFF_AL + ro + 8 * ROWB + 16);
            }
            uint32_t bh[8][2], bl[8][2];
#pragma unroll
            for (int nj = 0; nj < 8; nj++) {
                int bo = (c0 + nj * 8 + qr) * ROWB + (kb + 2 * qc) * 2;
                bh[nj][0] = *(const uint32_t*)(sm + OFF_BH + bo);
                bh[nj][1] = *(const uint32_t*)(sm + OFF_BH + bo + 16);
                bl[nj][0] = *(const uint32_t*)(sm + OFF_BL + bo);
                bl[nj][1] = *(const uint32_t*)(sm + OFF_BL + bo + 16);
            }
#pragma unroll
            for (int mi = 0; mi < 2; mi++)
#pragma unroll
                for (int nj = 0; nj < 8; nj++) {
                    mma_bf16(d[mi][nj], ah[mi], bh[nj]);
                    mma_bf16(d[mi][nj], al[mi], bh[nj]);
                    mma_bf16(d[mi][nj], ah[mi], bl[nj]);
                }
        }
    }

    // ---- epilogue: bias + relu, float2 stores ----
#pragma unroll
    for (int mi = 0; mi < 2; mi++) {
        int rlo = row0 + r0 + mi * 16 + qr;
        int rhi = rlo + 8;
#pragma unroll
        for (int nj = 0; nj < 8; nj++) {
            int gc = c0 + nj * 8 + 2 * qc;
            float b0v = s_bias[gc], b1v = s_bias[gc + 1];
            if (rlo < N_NODES) {
                float2 o;
                o.x = fmaxf(d[mi][nj][0] + b0v, 0.f);
                o.y = fmaxf(d[mi][nj][1] + b1v, 0.f);
                *(float2*)(g_h + (size_t)rlo * 128 + gc) = o;
            }
            if (rhi < N_NODES) {
                float2 o;
                o.x = fmaxf(d[mi][nj][2] + b0v, 0.f);
                o.y = fmaxf(d[mi][nj][3] + b1v, 0.f);
                *(float2*)(g_h + (size_t)rhi * 128 + gc) = o;
            }
        }
    }
}

// ---------------- kernel 3: t = h@W2l (-> g_t), r = h@W2r (-> d_out staging) -
__global__ void __launch_bounds__(256)
gemm2_kernel(const float* __restrict__ W2l, const float* __restrict__ W2r,
             float* __restrict__ outr) {
    __shared__ float Wsh[128 * 32];
    __shared__ float Ash[64 * 128];
    int tid = threadIdx.x;
    int row0 = blockIdx.x * 64;

    for (int i = tid; i < 128 * 16; i += 256) {
        int k = i >> 4, c = i & 15;
        Wsh[k * 32 + c]      = W2l[i];
        Wsh[k * 32 + 16 + c] = W2r[i];
    }
    for (int idx = tid; idx < 64 * 32; idx += 256) {   // float4 units
        int r = idx >> 5, q = idx & 31;
        int gi = row0 + r;
        float4 v = (gi < N_NODES) ? g_h4[(size_t)gi * 32 + q]
                                  : make_float4(0.f, 0.f, 0.f, 0.f);
        ((float4*)(Ash + r * 128))[q] = v;
    }
    __syncthreads();

    int warp = tid >> 5, lane = tid & 31;
    int r0 = warp * 8;
    float acc[8] = {0.f, 0.f, 0.f, 0.f, 0.f, 0.f, 0.f, 0.f};

    for (int k = 0; k < 128; k += 4) {
        float4 a4[8];
#pragma unroll
        for (int r = 0; r < 8; r++)
            a4[r] = *(const float4*)(Ash + (r0 + r) * 128 + k);
#pragma unroll
        for (int kk = 0; kk < 4; kk++) {
            float w = Wsh[(k + kk) * 32 + lane];
#pragma unroll
            for (int r = 0; r < 8; r++) {
                float a = (kk == 0) ? a4[r].x : (kk == 1) ? a4[r].y
                         : (kk == 2) ? a4[r].z : a4[r].w;
                acc[r] = fmaf(a, w, acc[r]);
            }
        }
    }
#pragma unroll
    for (int r = 0; r < 8; r++) {
        int gi = row0 + r0 + r;
        if (gi >= N_NODES) continue;
        if (lane < 16) g_t[(size_t)gi * CLS + lane] = acc[r];
        else           outr[(size_t)gi * CLS + (lane - 16)] = acc[r];
    }
}

// ---------------- kernel 4: gather-sum t over CSR -> g_agg2 (sum) -----------
// 4 lanes per dst node (one float4 each of the 16-float row)
__global__ void __launch_bounds__(256)
gather2_kernel() {
    int id = blockIdx.x * blockDim.x + threadIdx.x;
    int node = id >> 2;
    int l = id & 3;
    if (node >= N_NODES) return;
    int beg = g_off[node];
    int deg = g_degi[node];
    float4 acc = make_float4(0.f, 0.f, 0.f, 0.f);
    for (int j = 0; j < deg; j++) {
        int s = g_eid[beg + j];
        float4 v = g_t4[(size_t)s * 4 + l];
        acc.x += v.x; acc.y += v.y; acc.z += v.z; acc.w += v.w;
    }
    g_agg24[(size_t)node * 4 + l] = acc;
}

// ---------------- kernel 5: out = log_softmax(r + b2 + agg2/deg) ------------
__global__ void __launch_bounds__(256)
final_kernel(float* __restrict__ out, const float* __restrict__ b2) {
    int idx = blockIdx.x * blockDim.x + threadIdx.x;
    int row = idx >> 4;
    int c = idx & 15;
    if (row >= N_NODES) return;
    float invd = 1.0f / fmaxf(g_deg[row], 1.0f);
    float v = out[(size_t)row * CLS + c] + b2[c]
            + g_agg2[(size_t)row * CLS + c] * invd;
    float m = v;
#pragma unroll
    for (int o = 8; o > 0; o >>= 1)
        m = fmaxf(m, __shfl_xor_sync(0xffffffffu, m, o, 16));
    float e = __expf(v - m);
    float ssum = e;
#pragma unroll
    for (int o = 8; o > 0; o >>= 1)
        ssum += __shfl_xor_sync(0xffffffffu, ssum, o, 16);
    out[(size_t)row * CLS + c] = v - m - __logf(ssum);
}

// ---------------- launch ----------------------------------------------------
extern "C" void kernel_launch(void* const* d_in, const int* in_sizes, int n_in,
                              void* d_out, int out_size) {
    const float* x   = (const float*)d_in[0];
    const int*   ew  = (const int*)d_in[1];      // edge_index raw 32-bit words
    const float* W1l = (const float*)d_in[2];
    const float* b1  = (const float*)d_in[3];
    const float* W1r = (const float*)d_in[4];
    const float* W2l = (const float*)d_in[5];
    const float* b2  = (const float*)d_in[6];
    const float* W2r = (const float*)d_in[7];
    float* out = (float*)d_out;

    void* p_degi;
    cudaGetSymbolAddress(&p_degi, g_degi);
    cudaMemsetAsync(p_degi, 0, sizeof(int) * N_NODES);

    detect_kernel<<<1, 256>>>(ew);
    decode_kernel<<<(N_EDGES + 255) / 256, 256>>>(ew);
    scan_kernel<<<1, 1024>>>();
    place_kernel<<<(N_EDGES + 255) / 256, 256>>>();
    wconv_kernel<<<(2 * 128 * 128 + 255) / 256, 256>>>(W1l, W1r);

    gather1_kernel<<<(N_NODES * 32 + 255) / 256, 256>>>(x);

    cudaFuncSetAttribute(gemm1_kernel, cudaFuncAttributeMaxDynamicSharedMemorySize,
                         SMEM_G1);
    gemm1_kernel<<<(N_NODES + 127) / 128, 256, SMEM_G1>>>(x, b1);

    gemm2_kernel<<<(N_NODES + 63) / 64, 256>>>(W2l, W2r, out);

    gather2_kernel<<<(N_NODES * 4 + 255) / 256, 256>>>();

    final_kernel<<<(N_NODES * CLS) / 256, 256>>>(out, b2);
}

// round 13
// speedup vs baseline: 1.6417x; 1.6417x over previous
#include <cuda_runtime.h>
#include <cuda_bf16.h>
#include <cstdint>

#define N_NODES 100000
#define N_EDGES 600000
#define F_IN 128
#define HID 128
#define CLS 16

// ---------------- scratch (device globals: no allocation allowed) ----------
__device__ float g_deg[N_NODES];                          // in-degree (float)
__device__ float4 g_agg4[(size_t)N_NODES * F_IN / 4];     // layer-1 neighbor sum
__device__ float4 g_h4[(size_t)N_NODES * HID / 4];        // layer-1 output
__device__ float4 g_t4[(size_t)N_NODES * CLS / 4];        // h @ W2_l (pre-aggregation)
__device__ float4 g_agg24[(size_t)N_NODES * CLS / 4];     // layer-2 neighbor sum of t
__device__ int g_src[N_EDGES];
__device__ int g_dst[N_EDGES];
__device__ int g_fmt64;                                    // 1 if edge_index is int64
// bf16 hi/lo images of W1l/W1r as B[n][k] (k contiguous = col-major for mma.sync)
__device__ __align__(16) uint16_t g_Bh_img[2][128 * 128];
__device__ __align__(16) uint16_t g_Bl_img[2][128 * 128];

#define g_h    ((float*)g_h4)
#define g_t    ((float*)g_t4)
#define g_agg2 ((float*)g_agg24)

// ---------------- mma.sync helper (portable sm_80+ HMMA path) ---------------
__device__ __forceinline__ void mma_bf16(float* d, const uint32_t* a,
                                         const uint32_t* b) {
    asm volatile(
        "mma.sync.aligned.m16n8k16.row.col.f32.bf16.bf16.f32 "
        "{%0,%1,%2,%3}, {%4,%5,%6,%7}, {%8,%9}, {%0,%1,%2,%3};"
        : "+f"(d[0]), "+f"(d[1]), "+f"(d[2]), "+f"(d[3])
        : "r"(a[0]), "r"(a[1]), "r"(a[2]), "r"(a[3]), "r"(b[0]), "r"(b[1]));
}

// smem layout for gemm1 (64-row CTA, 2 CTAs/SM):
// A panels 64x136 bf16 (hi, lo), B panels 128x136 bf16 (hi, lo)
#define PADK 136
#define ROWB (PADK * 2)            // 272 bytes per row
#define ASZ_A (64 * ROWB)          // 17408 bytes
#define ASZ_B (128 * ROWB)         // 34816 bytes
#define OFF_AH 0
#define OFF_AL (ASZ_A)
#define OFF_BH (2 * ASZ_A)
#define OFF_BL (2 * ASZ_A + ASZ_B)
#define SMEM_G1 (2 * ASZ_A + 2 * ASZ_B)   // 104448 bytes -> 2 CTAs/SM

// ---------------- kernel 0a: detect edge_index dtype ------------------------
__global__ void detect_kernel(const int* __restrict__ ew) {
    __shared__ int sacc[256];
    int acc = 0;
    for (int i = threadIdx.x; i < 4096; i += 256)
        acc |= ew[2 * i + 1];
    sacc[threadIdx.x] = acc;
    __syncthreads();
    if (threadIdx.x == 0) {
        int t = 0;
        for (int i = 0; i < 256; i++) t |= sacc[i];
        g_fmt64 = (t == 0) ? 1 : 0;
    }
}

// ---------------- kernel 0b: decode edge list to int32 src/dst --------------
__global__ void __launch_bounds__(256)
decode_kernel(const int* __restrict__ ew) {
    int e = blockIdx.x * blockDim.x + threadIdx.x;
    if (e >= N_EDGES) return;
    if (g_fmt64) {
        g_src[e] = ew[2 * e];
        g_dst[e] = ew[2 * (N_EDGES + e)];
    } else {
        g_src[e] = ew[e];
        g_dst[e] = ew[N_EDGES + e];
    }
}

// ---------------- kernel 0c: convert W1l/W1r -> bf16 hi/lo B[n][k] ----------
__global__ void __launch_bounds__(256)
wconv_kernel(const float* __restrict__ W1l, const float* __restrict__ W1r) {
    int id = blockIdx.x * blockDim.x + threadIdx.x;
    if (id >= 2 * 128 * 128) return;
    int p = id >> 14, rem = id & 16383;
    int n = rem >> 7, k = rem & 127;
    const float* W = p ? W1r : W1l;
    float w = W[k * 128 + n];                 // W[k][n] -> B[n][k]
    __nv_bfloat16 h = __float2bfloat16(w);
    __nv_bfloat16 l = __float2bfloat16(w - __bfloat162float(h));
    g_Bh_img[p][n * 128 + k] = *(uint16_t*)&h;
    g_Bl_img[p][n * 128 + k] = *(uint16_t*)&l;
}

// ---------------- kernel 1: scatter x[src] -> agg[dst], deg[dst]++ ----------
// one warp per edge; each lane moves one float4 (128-bit vector atomic)
__global__ void __launch_bounds__(256)
scatter1_kernel(const float* __restrict__ x) {
    int gtid = blockIdx.x * blockDim.x + threadIdx.x;
    int e = gtid >> 5;
    int lane = gtid & 31;
    if (e >= N_EDGES) return;
    int s = g_src[e];
    int d = g_dst[e];
    float4 v = ((const float4*)(x + (size_t)s * F_IN))[lane];
    atomicAdd(&g_agg4[(size_t)d * (F_IN / 4) + lane], v);
    if (lane == 0) atomicAdd(&g_deg[d], 1.0f);
}

// ---------------- kernel 2: h = relu((agg*invd)@W1l + b1 + x@W1r) -----------
// mma.sync bf16 3-term split GEMM. CTA = 64x128 tile, 256 threads, 8 warps
// (4m x 2n), warp tile 16x64. 102KB smem -> 2 CTAs/SM so conversion/sync of
// one CTA overlaps the MMA mainloop of the other. K=256 in two phases.
__global__ void __launch_bounds__(256, 2)
gemm1_kernel(const float* __restrict__ x, const float* __restrict__ b1) {
    extern __shared__ __align__(16) char sm[];
    __shared__ float s_bias[128];
    __shared__ float s_invd[64];

    int tid = threadIdx.x, wid = tid >> 5, lane = tid & 31;
    int qr = lane >> 2, qc = lane & 3;
    int row0 = blockIdx.x * 64;
    int r0 = (wid & 3) * 16;       // warp m-offset (4 slots of 16 rows)
    int c0 = (wid >> 2) * 64;      // warp n-offset (2 slots of 64 cols)

    if (tid < 128) s_bias[tid] = b1[tid];
    if (tid < 64) {
        int gi = row0 + tid;
        float dg = (gi < N_NODES) ? g_deg[gi] : 1.0f;
        s_invd[tid] = 1.0f / fmaxf(dg, 1.0f);
    }

    float d[8][4];
#pragma unroll
    for (int nj = 0; nj < 8; nj++)
#pragma unroll
        for (int v = 0; v < 4; v++) d[nj][v] = 0.f;

#pragma unroll 1
    for (int phase = 0; phase < 2; phase++) {
        __syncthreads();   // protect smem reuse across phases (and invd init)

        // ---- A conversion: fp32 -> bf16 hi/lo into padded panels (64 rows) --
        for (int f = tid; f < 64 * 32; f += 256) {
            int r = f >> 5, q = f & 31;          // q = float4 index over k
            int gi = row0 + r;
            float4 v = make_float4(0.f, 0.f, 0.f, 0.f);
            if (gi < N_NODES) {
                if (phase == 0) {
                    v = g_agg4[(size_t)gi * 32 + q];
                    float s = s_invd[r];
                    v.x *= s; v.y *= s; v.z *= s; v.w *= s;
                } else {
                    v = ((const float4*)(x + (size_t)gi * 128))[q];
                }
            }
            __nv_bfloat16 h0 = __float2bfloat16(v.x), h1 = __float2bfloat16(v.y);
            __nv_bfloat16 h2 = __float2bfloat16(v.z), h3 = __float2bfloat16(v.w);
            __nv_bfloat16 l0 = __float2bfloat16(v.x - __bfloat162float(h0));
            __nv_bfloat16 l1 = __float2bfloat16(v.y - __bfloat162float(h1));
            __nv_bfloat16 l2 = __float2bfloat16(v.z - __bfloat162float(h2));
            __nv_bfloat16 l3 = __float2bfloat16(v.w - __bfloat162float(h3));
            uint64_t hp = (uint64_t)(*(uint16_t*)&h0)
                        | ((uint64_t)(*(uint16_t*)&h1) << 16)
                        | ((uint64_t)(*(uint16_t*)&h2) << 32)
                        | ((uint64_t)(*(uint16_t*)&h3) << 48);
            uint64_t lp = (uint64_t)(*(uint16_t*)&l0)
                        | ((uint64_t)(*(uint16_t*)&l1) << 16)
                        | ((uint64_t)(*(uint16_t*)&l2) << 32)
                        | ((uint64_t)(*(uint16_t*)&l3) << 48);
            int off = r * ROWB + q * 8;          // q*4 bf16 = 8 bytes
            *(uint64_t*)(sm + OFF_AH + off) = hp;
            *(uint64_t*)(sm + OFF_AL + off) = lp;
        }
        // ---- B copy: unpadded [n][128] images -> padded panels (128 rows) --
        for (int i = tid; i < 2048; i += 256) {  // 128 rows x 16 float4
            int r = i >> 4, w = i & 15;
            int dst = r * ROWB + w * 16;
            *(float4*)(sm + OFF_BH + dst) = ((const float4*)g_Bh_img[phase])[i];
            *(float4*)(sm + OFF_BL + dst) = ((const float4*)g_Bl_img[phase])[i];
        }
        __syncthreads();

        // ---- mainloop: 8 k16-steps ----
#pragma unroll 1
        for (int ks = 0; ks < 8; ks++) {
            int kb = ks * 16;
            uint32_t ah[4], al[4];
            {
                int ro = (r0 + qr) * ROWB + (kb + 2 * qc) * 2;
                ah[0] = *(const uint32_t*)(sm + OFF_AH + ro);
                ah[1] = *(const uint32_t*)(sm + OFF_AH + ro + 8 * ROWB);
                ah[2] = *(const uint32_t*)(sm + OFF_AH + ro + 16);
                ah[3] = *(const uint32_t*)(sm + OFF_AH + ro + 8 * ROWB + 16);
                al[0] = *(const uint32_t*)(sm + OFF_AL + ro);
                al[1] = *(const uint32_t*)(sm + OFF_AL + ro + 8 * ROWB);
                al[2] = *(const uint32_t*)(sm + OFF_AL + ro + 16);
                al[3] = *(const uint32_t*)(sm + OFF_AL + ro + 8 * ROWB + 16);
            }
            uint32_t bh[8][2], bl[8][2];
#pragma unroll
            for (int nj = 0; nj < 8; nj++) {
                int bo = (c0 + nj * 8 + qr) * ROWB + (kb + 2 * qc) * 2;
                bh[nj][0] = *(const uint32_t*)(sm + OFF_BH + bo);
                bh[nj][1] = *(const uint32_t*)(sm + OFF_BH + bo + 16);
                bl[nj][0] = *(const uint32_t*)(sm + OFF_BL + bo);
                bl[nj][1] = *(const uint32_t*)(sm + OFF_BL + bo + 16);
            }
#pragma unroll
            for (int nj = 0; nj < 8; nj++) {
                mma_bf16(d[nj], ah, bh[nj]);
                mma_bf16(d[nj], al, bh[nj]);
                mma_bf16(d[nj], ah, bl[nj]);
            }
        }
    }

    // ---- epilogue: bias + relu, float2 stores ----
    {
        int rlo = row0 + r0 + qr;
        int rhi = rlo + 8;
#pragma unroll
        for (int nj = 0; nj < 8; nj++) {
            int gc = c0 + nj * 8 + 2 * qc;
            float b0v = s_bias[gc], b1v = s_bias[gc + 1];
            if (rlo < N_NODES) {
                float2 o;
                o.x = fmaxf(d[nj][0] + b0v, 0.f);
                o.y = fmaxf(d[nj][1] + b1v, 0.f);
                *(float2*)(g_h + (size_t)rlo * 128 + gc) = o;
            }
            if (rhi < N_NODES) {
                float2 o;
                o.x = fmaxf(d[nj][2] + b0v, 0.f);
                o.y = fmaxf(d[nj][3] + b1v, 0.f);
                *(float2*)(g_h + (size_t)rhi * 128 + gc) = o;
            }
        }
    }
}

// ---------------- kernel 3: t = h@W2l (-> g_t), r = h@W2r (-> d_out staging) -
__global__ void __launch_bounds__(256)
gemm2_kernel(const float* __restrict__ W2l, const float* __restrict__ W2r,
             float* __restrict__ outr) {
    __shared__ float Wsh[128 * 32];
    __shared__ float Ash[64 * 128];
    int tid = threadIdx.x;
    int row0 = blockIdx.x * 64;

    for (int i = tid; i < 128 * 16; i += 256) {
        int k = i >> 4, c = i & 15;
        Wsh[k * 32 + c]      = W2l[i];
        Wsh[k * 32 + 16 + c] = W2r[i];
    }
    for (int idx = tid; idx < 64 * 32; idx += 256) {   // float4 units
        int r = idx >> 5, q = idx & 31;
        int gi = row0 + r;
        float4 v = (gi < N_NODES) ? g_h4[(size_t)gi * 32 + q]
                                  : make_float4(0.f, 0.f, 0.f, 0.f);
        ((float4*)(Ash + r * 128))[q] = v;
    }
    __syncthreads();

    int warp = tid >> 5, lane = tid & 31;
    int r0 = warp * 8;
    float acc[8] = {0.f, 0.f, 0.f, 0.f, 0.f, 0.f, 0.f, 0.f};

    for (int k = 0; k < 128; k += 4) {
        float4 a4[8];
#pragma unroll
        for (int r = 0; r < 8; r++)
            a4[r] = *(const float4*)(Ash + (r0 + r) * 128 + k);
#pragma unroll
        for (int kk = 0; kk < 4; kk++) {
            float w = Wsh[(k + kk) * 32 + lane];
#pragma unroll
            for (int r = 0; r < 8; r++) {
                float a = (kk == 0) ? a4[r].x : (kk == 1) ? a4[r].y
                         : (kk == 2) ? a4[r].z : a4[r].w;
                acc[r] = fmaf(a, w, acc[r]);
            }
        }
    }
#pragma unroll
    for (int r = 0; r < 8; r++) {
        int gi = row0 + r0 + r;
        if (gi >= N_NODES) continue;
        if (lane < 16) g_t[(size_t)gi * CLS + lane] = acc[r];
        else           outr[(size_t)gi * CLS + (lane - 16)] = acc[r];
    }
}

// ---------------- kernel 4: scatter t[src] -> agg2[dst] (16 floats/edge) ----
__global__ void __launch_bounds__(256)
scatter2_kernel() {
    int idx = blockIdx.x * blockDim.x + threadIdx.x;
    int e = idx >> 2;
    if (e >= N_EDGES) return;
    int l = idx & 3;
    int s = g_src[e];
    int d = g_dst[e];
    float4 v = g_t4[(size_t)s * (CLS / 4) + l];
    atomicAdd(&g_agg24[(size_t)d * (CLS / 4) + l], v);
}

// ---------------- kernel 5: out = log_softmax(r + b2 + agg2/deg) ------------
__global__ void __launch_bounds__(256)
final_kernel(float* __restrict__ out, const float* __restrict__ b2) {
    int idx = blockIdx.x * blockDim.x + threadIdx.x;
    int row = idx >> 4;
    int c = idx & 15;
    if (row >= N_NODES) return;
    float invd = 1.0f / fmaxf(g_deg[row], 1.0f);
    float v = out[(size_t)row * CLS + c] + b2[c]
            + g_agg2[(size_t)row * CLS + c] * invd;
    float m = v;
#pragma unroll
    for (int o = 8; o > 0; o >>= 1)
        m = fmaxf(m, __shfl_xor_sync(0xffffffffu, m, o, 16));
    float e = __expf(v - m);
    float ssum = e;
#pragma unroll
    for (int o = 8; o > 0; o >>= 1)
        ssum += __shfl_xor_sync(0xffffffffu, ssum, o, 16);
    out[(size_t)row * CLS + c] = v - m - __logf(ssum);
}

// ---------------- launch ----------------------------------------------------
extern "C" void kernel_launch(void* const* d_in, const int* in_sizes, int n_in,
                              void* d_out, int out_size) {
    const float* x   = (const float*)d_in[0];
    const int*   ew  = (const int*)d_in[1];      // edge_index raw 32-bit words
    const float* W1l = (const float*)d_in[2];
    const float* b1  = (const float*)d_in[3];
    const float* W1r = (const float*)d_in[4];
    const float* W2l = (const float*)d_in[5];
    const float* b2  = (const float*)d_in[6];
    const float* W2r = (const float*)d_in[7];
    float* out = (float*)d_out;

    void *p_deg, *p_agg, *p_agg2;
    cudaGetSymbolAddress(&p_deg,  g_deg);
    cudaGetSymbolAddress(&p_agg,  g_agg4);
    cudaGetSymbolAddress(&p_agg2, g_agg24);
    cudaMemsetAsync(p_deg,  0, sizeof(float) * N_NODES);
    cudaMemsetAsync(p_agg,  0, sizeof(float) * (size_t)N_NODES * F_IN);
    cudaMemsetAsync(p_agg2, 0, sizeof(float) * (size_t)N_NODES * CLS);

    detect_kernel<<<1, 256>>>(ew);
    decode_kernel<<<(N_EDGES + 255) / 256, 256>>>(ew);
    wconv_kernel<<<(2 * 128 * 128 + 255) / 256, 256>>>(W1l, W1r);

    scatter1_kernel<<<(N_EDGES * 32) / 256, 256>>>(x);

    cudaFuncSetAttribute(gemm1_kernel, cudaFuncAttributeMaxDynamicSharedMemorySize,
                         SMEM_G1);
    gemm1_kernel<<<(N_NODES + 63) / 64, 256, SMEM_G1>>>(x, b1);

    gemm2_kernel<<<(N_NODES + 63) / 64, 256>>>(W2l, W2r, out);

    scatter2_kernel<<<(N_EDGES * 4 + 255) / 256, 256>>>();

    final_kernel<<<(N_NODES * CLS) / 256, 256>>>(out, b2);
}

// round 14
// speedup vs baseline: 1.6682x; 1.0161x over previous
#include <cuda_runtime.h>
#include <cuda_bf16.h>
#include <cstdint>

#define N_NODES 100000
#define N_EDGES 600000
#define F_IN 128
#define HID 128
#define CLS 16

// ---------------- scratch (device globals: no allocation allowed) ----------
__device__ float g_deg[N_NODES];                          // in-degree (float)
__device__ float4 g_agg4[(size_t)N_NODES * F_IN / 4];     // layer-1 neighbor sum
__device__ float4 g_h4[(size_t)N_NODES * HID / 4];        // layer-1 output
__device__ float4 g_t4[(size_t)N_NODES * CLS / 4];        // h @ W2_l (pre-aggregation)
__device__ float4 g_agg24[(size_t)N_NODES * CLS / 4];     // layer-2 neighbor sum of t
__device__ int g_src[N_EDGES];
__device__ int g_dst[N_EDGES];
__device__ int g_fmt64;                                    // 1 if edge_index is int64
// bf16 hi/lo images of W1l/W1r as B[n][k] (k contiguous = col-major for mma.sync)
__device__ __align__(16) uint16_t g_Bh_img[2][128 * 128];
__device__ __align__(16) uint16_t g_Bl_img[2][128 * 128];

#define g_h    ((float*)g_h4)
#define g_t    ((float*)g_t4)
#define g_agg2 ((float*)g_agg24)

// ---------------- mma.sync helpers (portable sm_80+ HMMA path) --------------
__device__ __forceinline__ void mma_bf16(float* d, const uint32_t* a,
                                         const uint32_t* b) {
    asm volatile(
        "mma.sync.aligned.m16n8k16.row.col.f32.bf16.bf16.f32 "
        "{%0,%1,%2,%3}, {%4,%5,%6,%7}, {%8,%9}, {%0,%1,%2,%3};"
        : "+f"(d[0]), "+f"(d[1]), "+f"(d[2]), "+f"(d[3])
        : "r"(a[0]), "r"(a[1]), "r"(a[2]), "r"(a[3]), "r"(b[0]), "r"(b[1]));
}
__device__ __forceinline__ void ldsm4(uint32_t* r, uint32_t addr) {
    asm volatile(
        "ldmatrix.sync.aligned.m8n8.x4.shared.b16 {%0,%1,%2,%3}, [%4];"
        : "=r"(r[0]), "=r"(r[1]), "=r"(r[2]), "=r"(r[3]) : "r"(addr));
}
__device__ __forceinline__ uint32_t smem_u32(const void* p) {
    uint32_t a;
    asm("{ .reg .u64 t; cvta.to.shared.u64 t, %1; cvt.u32.u64 %0, t; }"
        : "=r"(a) : "l"(p));
    return a;
}

// smem layout for gemm1 (64-row CTA, 2 CTAs/SM):
// A panels 64x136 bf16 (hi, lo), B panels 128x136 bf16 (hi, lo)
#define PADK 136
#define ROWB (PADK * 2)            // 272 bytes per row
#define ASZ_A (64 * ROWB)          // 17408 bytes
#define ASZ_B (128 * ROWB)         // 34816 bytes
#define OFF_AH 0
#define OFF_AL (ASZ_A)
#define OFF_BH (2 * ASZ_A)
#define OFF_BL (2 * ASZ_A + ASZ_B)
#define SMEM_G1 (2 * ASZ_A + 2 * ASZ_B)   // 104448 bytes -> 2 CTAs/SM

// ---------------- kernel 0a: detect edge_index dtype ------------------------
__global__ void detect_kernel(const int* __restrict__ ew) {
    __shared__ int sacc[256];
    int acc = 0;
    for (int i = threadIdx.x; i < 4096; i += 256)
        acc |= ew[2 * i + 1];
    sacc[threadIdx.x] = acc;
    __syncthreads();
    if (threadIdx.x == 0) {
        int t = 0;
        for (int i = 0; i < 256; i++) t |= sacc[i];
        g_fmt64 = (t == 0) ? 1 : 0;
    }
}

// ---------------- kernel 0b: decode edge list to int32 src/dst --------------
__global__ void __launch_bounds__(256)
decode_kernel(const int* __restrict__ ew) {
    int e = blockIdx.x * blockDim.x + threadIdx.x;
    if (e >= N_EDGES) return;
    if (g_fmt64) {
        g_src[e] = ew[2 * e];
        g_dst[e] = ew[2 * (N_EDGES + e)];
    } else {
        g_src[e] = ew[e];
        g_dst[e] = ew[N_EDGES + e];
    }
}

// ---------------- kernel 0c: convert W1l/W1r -> bf16 hi/lo B[n][k] ----------
__global__ void __launch_bounds__(256)
wconv_kernel(const float* __restrict__ W1l, const float* __restrict__ W1r) {
    int id = blockIdx.x * blockDim.x + threadIdx.x;
    if (id >= 2 * 128 * 128) return;
    int p = id >> 14, rem = id & 16383;
    int n = rem >> 7, k = rem & 127;
    const float* W = p ? W1r : W1l;
    float w = W[k * 128 + n];                 // W[k][n] -> B[n][k]
    __nv_bfloat16 h = __float2bfloat16(w);
    __nv_bfloat16 l = __float2bfloat16(w - __bfloat162float(h));
    g_Bh_img[p][n * 128 + k] = *(uint16_t*)&h;
    g_Bl_img[p][n * 128 + k] = *(uint16_t*)&l;
}

// ---------------- kernel 1: scatter x[src] -> agg[dst], deg[dst]++ ----------
// one warp per edge; each lane moves one float4 (128-bit vector atomic)
__global__ void __launch_bounds__(256)
scatter1_kernel(const float* __restrict__ x) {
    int gtid = blockIdx.x * blockDim.x + threadIdx.x;
    int e = gtid >> 5;
    int lane = gtid & 31;
    if (e >= N_EDGES) return;
    int s = g_src[e];
    int d = g_dst[e];
    float4 v = ((const float4*)(x + (size_t)s * F_IN))[lane];
    atomicAdd(&g_agg4[(size_t)d * (F_IN / 4) + lane], v);
    if (lane == 0) atomicAdd(&g_deg[d], 1.0f);
}

// ---------------- kernel 2: h = relu((agg*invd)@W1l + b1 + x@W1r) -----------
// mma.sync bf16 3-term split GEMM. CTA = 64x128 tile, 256 threads, 8 warps
// (4m x 2n), warp tile 16x64. 102KB smem -> 2 CTAs/SM. K=256 in two phases.
// Fragments loaded via ldmatrix.x4 (same layout as the scalar loads this
// replaces: lane l holds (row l/4, col 2(l%4)) of each 8x8 matrix).
__global__ void __launch_bounds__(256, 2)
gemm1_kernel(const float* __restrict__ x, const float* __restrict__ b1) {
    extern __shared__ __align__(16) char sm[];
    __shared__ float s_bias[128];
    __shared__ float s_invd[64];

    int tid = threadIdx.x, wid = tid >> 5, lane = tid & 31;
    int qr = lane >> 2, qc = lane & 3;
    int row0 = blockIdx.x * 64;
    int r0 = (wid & 3) * 16;       // warp m-offset (4 slots of 16 rows)
    int c0 = (wid >> 2) * 64;      // warp n-offset (2 slots of 64 cols)

    if (tid < 128) s_bias[tid] = b1[tid];
    if (tid < 64) {
        int gi = row0 + tid;
        float dg = (gi < N_NODES) ? g_deg[gi] : 1.0f;
        s_invd[tid] = 1.0f / fmaxf(dg, 1.0f);
    }

    uint32_t smb = smem_u32(sm);
    // ldmatrix per-lane base offsets (kb=0); advance by 32B per k16-step.
    // A x4: M0 rows m=r0..+7 k0..7 | M1 m+8 k0..7 | M2 m k8..15 | M3 m+8 k8..15
    uint32_t a_base = smb +
        (uint32_t)((r0 + ((lane >> 3) & 1) * 8 + (lane & 7)) * ROWB
                   + ((lane >> 4) & 1) * 16);
    // B x4 for nj-pair p: M0 n=c0+16p.. k0..7 | M1 same n k8..15
    //                     M2 n+8 k0..7 | M3 n+8 k8..15
    uint32_t b_base[4];
#pragma unroll
    for (int p = 0; p < 4; p++)
        b_base[p] = smb +
            (uint32_t)((c0 + 16 * p + ((lane >> 4) & 1) * 8 + (lane & 7)) * ROWB
                       + ((lane >> 3) & 1) * 16);

    float d[8][4];
#pragma unroll
    for (int nj = 0; nj < 8; nj++)
#pragma unroll
        for (int v = 0; v < 4; v++) d[nj][v] = 0.f;

#pragma unroll 1
    for (int phase = 0; phase < 2; phase++) {
        __syncthreads();   // protect smem reuse across phases (and invd init)

        // ---- A conversion: fp32 -> bf16 hi/lo into padded panels (64 rows) --
        for (int f = tid; f < 64 * 32; f += 256) {
            int r = f >> 5, q = f & 31;          // q = float4 index over k
            int gi = row0 + r;
            float4 v = make_float4(0.f, 0.f, 0.f, 0.f);
            if (gi < N_NODES) {
                if (phase == 0) {
                    v = g_agg4[(size_t)gi * 32 + q];
                    float s = s_invd[r];
                    v.x *= s; v.y *= s; v.z *= s; v.w *= s;
                } else {
                    v = ((const float4*)(x + (size_t)gi * 128))[q];
                }
            }
            __nv_bfloat16 h0 = __float2bfloat16(v.x), h1 = __float2bfloat16(v.y);
            __nv_bfloat16 h2 = __float2bfloat16(v.z), h3 = __float2bfloat16(v.w);
            __nv_bfloat16 l0 = __float2bfloat16(v.x - __bfloat162float(h0));
            __nv_bfloat16 l1 = __float2bfloat16(v.y - __bfloat162float(h1));
            __nv_bfloat16 l2 = __float2bfloat16(v.z - __bfloat162float(h2));
            __nv_bfloat16 l3 = __float2bfloat16(v.w - __bfloat162float(h3));
            uint64_t hp = (uint64_t)(*(uint16_t*)&h0)
                        | ((uint64_t)(*(uint16_t*)&h1) << 16)
                        | ((uint64_t)(*(uint16_t*)&h2) << 32)
                        | ((uint64_t)(*(uint16_t*)&h3) << 48);
            uint64_t lp = (uint64_t)(*(uint16_t*)&l0)
                        | ((uint64_t)(*(uint16_t*)&l1) << 16)
                        | ((uint64_t)(*(uint16_t*)&l2) << 32)
                        | ((uint64_t)(*(uint16_t*)&l3) << 48);
            int off = r * ROWB + q * 8;          // q*4 bf16 = 8 bytes
            *(uint64_t*)(sm + OFF_AH + off) = hp;
            *(uint64_t*)(sm + OFF_AL + off) = lp;
        }
        // ---- B copy: unpadded [n][128] images -> padded panels (128 rows) --
        for (int i = tid; i < 2048; i += 256) {  // 128 rows x 16 float4
            int r = i >> 4, w = i & 15;
            int dst = r * ROWB + w * 16;
            *(float4*)(sm + OFF_BH + dst) = ((const float4*)g_Bh_img[phase])[i];
            *(float4*)(sm + OFF_BL + dst) = ((const float4*)g_Bl_img[phase])[i];
        }
        __syncthreads();

        // ---- mainloop: 8 k16-steps, ldmatrix fragment loads ----
#pragma unroll 1
        for (int ks = 0; ks < 8; ks++) {
            uint32_t kadv = (uint32_t)(ks * 32);   // 16 bf16 = 32 bytes
            uint32_t ah[4], al[4];
            ldsm4(ah, a_base + OFF_AH + kadv);
            ldsm4(al, a_base + OFF_AL + kadv);
            uint32_t bh[4][4], bl[4][4];
#pragma unroll
            for (int p = 0; p < 4; p++) {
                ldsm4(bh[p], b_base[p] + OFF_BH + kadv);
                ldsm4(bl[p], b_base[p] + OFF_BL + kadv);
            }
#pragma unroll
            for (int p = 0; p < 4; p++) {
                mma_bf16(d[2 * p],     ah, &bh[p][0]);
                mma_bf16(d[2 * p],     al, &bh[p][0]);
                mma_bf16(d[2 * p],     ah, &bl[p][0]);
                mma_bf16(d[2 * p + 1], ah, &bh[p][2]);
                mma_bf16(d[2 * p + 1], al, &bh[p][2]);
                mma_bf16(d[2 * p + 1], ah, &bl[p][2]);
            }
        }
    }

    // ---- epilogue: bias + relu, float2 stores ----
    {
        int rlo = row0 + r0 + qr;
        int rhi = rlo + 8;
#pragma unroll
        for (int nj = 0; nj < 8; nj++) {
            int gc = c0 + nj * 8 + 2 * qc;
            float b0v = s_bias[gc], b1v = s_bias[gc + 1];
            if (rlo < N_NODES) {
                float2 o;
                o.x = fmaxf(d[nj][0] + b0v, 0.f);
                o.y = fmaxf(d[nj][1] + b1v, 0.f);
                *(float2*)(g_h + (size_t)rlo * 128 + gc) = o;
            }
            if (rhi < N_NODES) {
                float2 o;
                o.x = fmaxf(d[nj][2] + b0v, 0.f);
                o.y = fmaxf(d[nj][3] + b1v, 0.f);
                *(float2*)(g_h + (size_t)rhi * 128 + gc) = o;
            }
        }
    }
}

// ---------------- kernel 3: t = h@W2l (-> g_t), r = h@W2r (-> d_out staging) -
__global__ void __launch_bounds__(256)
gemm2_kernel(const float* __restrict__ W2l, const float* __restrict__ W2r,
             float* __restrict__ outr) {
    __shared__ float Wsh[128 * 32];
    __shared__ float Ash[64 * 128];
    int tid = threadIdx.x;
    int row0 = blockIdx.x * 64;

    for (int i = tid; i < 128 * 16; i += 256) {
        int k = i >> 4, c = i & 15;
        Wsh[k * 32 + c]      = W2l[i];
        Wsh[k * 32 + 16 + c] = W2r[i];
    }
    for (int idx = tid; idx < 64 * 32; idx += 256) {   // float4 units
        int r = idx >> 5, q = idx & 31;
        int gi = row0 + r;
        float4 v = (gi < N_NODES) ? g_h4[(size_t)gi * 32 + q]
                                  : make_float4(0.f, 0.f, 0.f, 0.f);
        ((float4*)(Ash + r * 128))[q] = v;
    }
    __syncthreads();

    int warp = tid >> 5, lane = tid & 31;
    int r0 = warp * 8;
    float acc[8] = {0.f, 0.f, 0.f, 0.f, 0.f, 0.f, 0.f, 0.f};

    for (int k = 0; k < 128; k += 4) {
        float4 a4[8];
#pragma unroll
        for (int r = 0; r < 8; r++)
            a4[r] = *(const float4*)(Ash + (r0 + r) * 128 + k);
#pragma unroll
        for (int kk = 0; kk < 4; kk++) {
            float w = Wsh[(k + kk) * 32 + lane];
#pragma unroll
            for (int r = 0; r < 8; r++) {
                float a = (kk == 0) ? a4[r].x : (kk == 1) ? a4[r].y
                         : (kk == 2) ? a4[r].z : a4[r].w;
                acc[r] = fmaf(a, w, acc[r]);
            }
        }
    }
#pragma unroll
    for (int r = 0; r < 8; r++) {
        int gi = row0 + r0 + r;
        if (gi >= N_NODES) continue;
        if (lane < 16) g_t[(size_t)gi * CLS + lane] = acc[r];
        else           outr[(size_t)gi * CLS + (lane - 16)] = acc[r];
    }
}

// ---------------- kernel 4: scatter t[src] -> agg2[dst] (16 floats/edge) ----
__global__ void __launch_bounds__(256)
scatter2_kernel() {
    int idx = blockIdx.x * blockDim.x + threadIdx.x;
    int e = idx >> 2;
    if (e >= N_EDGES) return;
    int l = idx & 3;
    int s = g_src[e];
    int d = g_dst[e];
    float4 v = g_t4[(size_t)s * (CLS / 4) + l];
    atomicAdd(&g_agg24[(size_t)d * (CLS / 4) + l], v);
}

// ---------------- kernel 5: out = log_softmax(r + b2 + agg2/deg) ------------
__global__ void __launch_bounds__(256)
final_kernel(float* __restrict__ out, const float* __restrict__ b2) {
    int idx = blockIdx.x * blockDim.x + threadIdx.x;
    int row = idx >> 4;
    int c = idx & 15;
    if (row >= N_NODES) return;
    float invd = 1.0f / fmaxf(g_deg[row], 1.0f);
    float v = out[(size_t)row * CLS + c] + b2[c]
            + g_agg2[(size_t)row * CLS + c] * invd;
    float m = v;
#pragma unroll
    for (int o = 8; o > 0; o >>= 1)
        m = fmaxf(m, __shfl_xor_sync(0xffffffffu, m, o, 16));
    float e = __expf(v - m);
    float ssum = e;
#pragma unroll
    for (int o = 8; o > 0; o >>= 1)
        ssum += __shfl_xor_sync(0xffffffffu, ssum, o, 16);
    out[(size_t)row * CLS + c] = v - m - __logf(ssum);
}

// ---------------- launch ----------------------------------------------------
extern "C" void kernel_launch(void* const* d_in, const int* in_sizes, int n_in,
                              void* d_out, int out_size) {
    const float* x   = (const float*)d_in[0];
    const int*   ew  = (const int*)d_in[1];      // edge_index raw 32-bit words
    const float* W1l = (const float*)d_in[2];
    const float* b1  = (const float*)d_in[3];
    const float* W1r = (const float*)d_in[4];
    const float* W2l = (const float*)d_in[5];
    const float* b2  = (const float*)d_in[6];
    const float* W2r = (const float*)d_in[7];
    float* out = (float*)d_out;

    void *p_deg, *p_agg, *p_agg2;
    cudaGetSymbolAddress(&p_deg,  g_deg);
    cudaGetSymbolAddress(&p_agg,  g_agg4);
    cudaGetSymbolAddress(&p_agg2, g_agg24);
    cudaMemsetAsync(p_deg,  0, sizeof(float) * N_NODES);
    cudaMemsetAsync(p_agg,  0, sizeof(float) * (size_t)N_NODES * F_IN);
    cudaMemsetAsync(p_agg2, 0, sizeof(float) * (size_t)N_NODES * CLS);

    detect_kernel<<<1, 256>>>(ew);
    decode_kernel<<<(N_EDGES + 255) / 256, 256>>>(ew);
    wconv_kernel<<<(2 * 128 * 128 + 255) / 256, 256>>>(W1l, W1r);

    scatter1_kernel<<<(N_EDGES * 32) / 256, 256>>>(x);

    cudaFuncSetAttribute(gemm1_kernel, cudaFuncAttributeMaxDynamicSharedMemorySize,
                         SMEM_G1);
    gemm1_kernel<<<(N_NODES + 63) / 64, 256, SMEM_G1>>>(x, b1);

    gemm2_kernel<<<(N_NODES + 63) / 64, 256>>>(W2l, W2r, out);

    scatter2_kernel<<<(N_EDGES * 4 + 255) / 256, 256>>>();

    final_kernel<<<(N_NODES * CLS) / 256, 256>>>(out, b2);
}